// round 3
// baseline (speedup 1.0000x reference)
#include <cuda_runtime.h>

#define NN 50000
#define NE 800000
#define DH 128
#define DOUT 64

// ---------------- device scratch (no allocations allowed) ----------------
__device__ float g_agg[NN * DH];
__device__ float g_h1[NN * DH];
__device__ float g_h2[NN * DH];
__device__ int   g_cnt[NN];
__device__ int   g_rowptr[NN + 1];
__device__ int   g_cursor[NN];
__device__ int   g_col[NE];
__device__ int   g_bsum[128];
__device__ float g_W12[DH * DOUT];
__device__ float g_b12[DOUT];
__device__ int   g_is64;

// ---------------- dtype detection (int64 vs int32 edge_index) ----------------
__global__ void k_detect(const int* __restrict__ ei32) {
    if (threadIdx.x == 0 && blockIdx.x == 0) {
        int odd_nonzero = 0;
        for (int i = 0; i < 64; i++)
            if (ei32[2 * i + 1] != 0) odd_nonzero++;
        g_is64 = (odd_nonzero == 0) ? 1 : 0;
    }
}

// ---------------- CSR build ----------------
__global__ void k_zero_cnt() {
    int i = blockIdx.x * blockDim.x + threadIdx.x;
    if (i < NN) g_cnt[i] = 0;
}

__global__ void k_hist(const int* __restrict__ ei32) {
    int e = blockIdx.x * blockDim.x + threadIdx.x;
    if (e >= NE) return;
    int d = g_is64 ? ei32[2 * (NE + e)] : ei32[NE + e];
    if (d >= 0 && d < NN) atomicAdd(&g_cnt[d], 1);
}

// inclusive scan per 512-block, block totals to g_bsum (98 blocks for NN=50000)
__global__ void k_scan1() {
    __shared__ int s[512];
    int i = blockIdx.x * 512 + threadIdx.x;
    int v = (i < NN) ? g_cnt[i] : 0;
    s[threadIdx.x] = v;
    __syncthreads();
    for (int off = 1; off < 512; off <<= 1) {
        int add = (threadIdx.x >= off) ? s[threadIdx.x - off] : 0;
        __syncthreads();
        s[threadIdx.x] += add;
        __syncthreads();
    }
    if (i < NN) g_rowptr[i + 1] = s[threadIdx.x];
    if (threadIdx.x == 511) g_bsum[blockIdx.x] = s[511];
}

// exclusive scan of 98 block sums (one block)
__global__ void k_scan2() {
    __shared__ int s[128];
    int t = threadIdx.x;
    int v = (t < 98) ? g_bsum[t] : 0;
    s[t] = v;
    __syncthreads();
    for (int off = 1; off < 128; off <<= 1) {
        int add = (t >= off) ? s[t - off] : 0;
        __syncthreads();
        s[t] += add;
        __syncthreads();
    }
    if (t < 98) g_bsum[t] = s[t] - v;  // exclusive
}

__global__ void k_scan3() {
    int i = blockIdx.x * 512 + threadIdx.x;
    if (i < NN) g_rowptr[i + 1] += g_bsum[blockIdx.x];
    if (i == 0) g_rowptr[0] = 0;
}

__global__ void k_cursor() {
    int i = blockIdx.x * blockDim.x + threadIdx.x;
    if (i < NN) g_cursor[i] = g_rowptr[i];
}

__global__ void k_scatter(const int* __restrict__ ei32) {
    int e = blockIdx.x * blockDim.x + threadIdx.x;
    if (e >= NE) return;
    int is64 = g_is64;
    int d = is64 ? ei32[2 * (NE + e)] : ei32[NE + e];
    int s = is64 ? ei32[2 * e] : ei32[e];
    if (d >= 0 && d < NN && s >= 0 && s < NN) {
        int p = atomicAdd(&g_cursor[d], 1);
        g_col[p] = s;
    }
}

// ---------------- fold post-MLP: W12 = W1@W2, b12 = b1@W2 + b2 ----------------
__global__ void k_w12(const float* __restrict__ W1, const float* __restrict__ W2,
                      const float* __restrict__ b1, const float* __restrict__ b2) {
    int idx = blockIdx.x * blockDim.x + threadIdx.x;
    if (idx < DH * DOUT) {
        int i = idx / DOUT, j = idx % DOUT;
        float s = 0.f;
        for (int k = 0; k < DH; k++) s += W1[i * DH + k] * W2[k * DOUT + j];
        g_W12[idx] = s;
    }
    if (idx < DOUT) {
        float s = b2[idx];
        for (int k = 0; k < DH; k++) s += b1[k] * W2[k * DOUT + idx];
        g_b12[idx] = s;
    }
}

// ---------------- mean aggregation: one warp per node ----------------
__global__ void k_agg(const float* __restrict__ in) {
    int w = (blockIdx.x * blockDim.x + threadIdx.x) >> 5;
    int lane = threadIdx.x & 31;
    if (w >= NN) return;
    int beg = g_rowptr[w], end = g_rowptr[w + 1];
    float4 acc = {0.f, 0.f, 0.f, 0.f};
    for (int e = beg; e < end; e++) {
        int s = g_col[e];
        float4 v = __ldg((const float4*)(in + (size_t)s * DH + lane * 4));
        acc.x += v.x; acc.y += v.y; acc.z += v.z; acc.w += v.w;
    }
    float inv = 1.0f / fmaxf((float)(end - beg), 1.0f);
    acc.x *= inv; acc.y *= inv; acc.z *= inv; acc.w *= inv;
    *(float4*)(g_agg + (size_t)w * DH + lane * 4) = acc;
}

// ---------------- fused GEMM: C = act( [A1|A2] @ [B1;B2] + bias ) ----------------
// A rows are always 128 wide. K total = 256 (DUAL) or 128.
template <int N, bool DUAL, bool RELU>
__launch_bounds__(256)
__global__ void k_gemm(const float* __restrict__ A1, const float* __restrict__ A2,
                       const float* __restrict__ B1, const float* __restrict__ B2,
                       const float* __restrict__ bias, float* __restrict__ C) {
    constexpr int KT  = DUAL ? 256 : 128;
    constexpr int KC  = 32;
    constexpr int TX  = N / 4;        // threads across cols (each does 4 cols)
    constexpr int TY  = 256 / TX;     // thread groups down rows
    constexpr int RPT = 64 / TY;      // rows per thread
    constexpr int AST = 68;           // padded row stride for As[k][row]

    __shared__ __align__(16) float As[KC * AST];
    __shared__ __align__(16) float Bs[KC][N];

    int t = threadIdx.x;
    int tx = t % TX, ty = t / TX;
    int row0 = ty * RPT;
    int col0 = tx * 4;
    int gr0 = blockIdx.x * 64;

    float acc[RPT][4];
#pragma unroll
    for (int r = 0; r < RPT; r++)
#pragma unroll
        for (int j = 0; j < 4; j++) acc[r][j] = 0.f;

    for (int k0 = 0; k0 < KT; k0 += KC) {
        const float* Asrc = (DUAL && k0 >= 128) ? A2 : A1;
        const float* Bsrc = (DUAL && k0 >= 128) ? B2 : B1;
        int kb = (DUAL && k0 >= 128) ? (k0 - 128) : k0;

        // stage A chunk transposed: As[k][row]
        {
            int kq = (t & 7) * 4;
            int r = t >> 3;  // 0..31
#pragma unroll
            for (int i = 0; i < 2; i++) {
                int rr = r + i * 32;
                int gr = gr0 + rr;
                float4 v = {0.f, 0.f, 0.f, 0.f};
                if (gr < NN) v = *(const float4*)(Asrc + (size_t)gr * 128 + kb + kq);
                As[(kq + 0) * AST + rr] = v.x;
                As[(kq + 1) * AST + rr] = v.y;
                As[(kq + 2) * AST + rr] = v.z;
                As[(kq + 3) * AST + rr] = v.w;
            }
        }
        // stage B chunk: Bs[k][n]
        {
            constexpr int NT4 = N / 4;
#pragma unroll
            for (int i = 0; i < (KC * NT4) / 256; i++) {
                int idx = t + i * 256;
                int kr = idx / NT4;
                int nc = (idx % NT4) * 4;
                *(float4*)&Bs[kr][nc] = *(const float4*)(Bsrc + (size_t)(kb + kr) * N + nc);
            }
        }
        __syncthreads();

#pragma unroll
        for (int kk = 0; kk < KC; kk++) {
            float4 b = *(float4*)&Bs[kk][col0];
            float a[RPT];
#pragma unroll
            for (int r4 = 0; r4 < RPT; r4 += 4) {
                float4 av = *(float4*)&As[kk * AST + row0 + r4];
                a[r4] = av.x; a[r4 + 1] = av.y; a[r4 + 2] = av.z; a[r4 + 3] = av.w;
            }
#pragma unroll
            for (int r = 0; r < RPT; r++) {
                acc[r][0] += a[r] * b.x;
                acc[r][1] += a[r] * b.y;
                acc[r][2] += a[r] * b.z;
                acc[r][3] += a[r] * b.w;
            }
        }
        __syncthreads();
    }

    float4 bv = *(const float4*)(bias + col0);
#pragma unroll
    for (int r = 0; r < RPT; r++) {
        int gr = gr0 + row0 + r;
        if (gr < NN) {
            float4 o;
            o.x = acc[r][0] + bv.x;
            o.y = acc[r][1] + bv.y;
            o.z = acc[r][2] + bv.z;
            o.w = acc[r][3] + bv.w;
            if (RELU) {
                o.x = fmaxf(o.x, 0.f); o.y = fmaxf(o.y, 0.f);
                o.z = fmaxf(o.z, 0.f); o.w = fmaxf(o.w, 0.f);
            }
            *(float4*)(C + (size_t)gr * N + col0) = o;
        }
    }
}

// ---------------- launch ----------------
extern "C" void kernel_launch(void* const* d_in, const int* in_sizes, int n_in,
                              void* d_out, int out_size) {
    const float* x    = (const float*)d_in[0];
    const int*   ei32 = (const int*)d_in[1];
    const float* Wl0 = (const float*)d_in[2];
    const float* bl0 = (const float*)d_in[3];
    const float* Wr0 = (const float*)d_in[4];
    const float* Wl1 = (const float*)d_in[5];
    const float* bl1 = (const float*)d_in[6];
    const float* Wr1 = (const float*)d_in[7];
    const float* Wl2 = (const float*)d_in[8];
    const float* bl2 = (const float*)d_in[9];
    const float* Wr2 = (const float*)d_in[10];
    const float* W1  = (const float*)d_in[11];
    const float* b1  = (const float*)d_in[12];
    const float* W2  = (const float*)d_in[13];
    const float* b2  = (const float*)d_in[14];
    float* out = (float*)d_out;

    float *agg, *h1, *h2, *W12, *b12;
    cudaGetSymbolAddress((void**)&agg, g_agg);
    cudaGetSymbolAddress((void**)&h1, g_h1);
    cudaGetSymbolAddress((void**)&h2, g_h2);
    cudaGetSymbolAddress((void**)&W12, g_W12);
    cudaGetSymbolAddress((void**)&b12, g_b12);

    // dtype probe + CSR build (per launch; deterministic work)
    k_detect<<<1, 32>>>(ei32);
    k_zero_cnt<<<(NN + 255) / 256, 256>>>();
    k_hist<<<(NE + 255) / 256, 256>>>(ei32);
    k_scan1<<<98, 512>>>();
    k_scan2<<<1, 128>>>();
    k_scan3<<<98, 512>>>();
    k_cursor<<<(NN + 255) / 256, 256>>>();
    k_scatter<<<(NE + 255) / 256, 256>>>(ei32);
    k_w12<<<(DH * DOUT + 255) / 256, 256>>>(W1, W2, b1, b2);

    const int aggBlocks = (NN * 32 + 255) / 256;
    const int gemmBlocks = (NN + 63) / 64;

    // layer 0
    k_agg<<<aggBlocks, 256>>>(x);
    k_gemm<128, true, true><<<gemmBlocks, 256>>>(agg, x, Wl0, Wr0, bl0, h1);
    // layer 1
    k_agg<<<aggBlocks, 256>>>(h1);
    k_gemm<128, true, true><<<gemmBlocks, 256>>>(agg, h1, Wl1, Wr1, bl1, h2);
    // layer 2
    k_agg<<<aggBlocks, 256>>>(h2);
    k_gemm<128, true, true><<<gemmBlocks, 256>>>(agg, h2, Wl2, Wr2, bl2, h1);
    // post MLP (folded)
    k_gemm<64, false, false><<<gemmBlocks, 256>>>(h1, nullptr, W12, nullptr, b12, out);
}

// round 5
// speedup vs baseline: 1.3022x; 1.3022x over previous
#include <cuda_runtime.h>
#include <cuda_bf16.h>
#include <cstdint>

#define NN 50000
#define NE 800000
#define DH 128
#define DOUT 64

// ---------------- device scratch (no allocations allowed) ----------------
__device__ int   g_cnt[NN];
__device__ int   g_rowptr[NN + 1];
__device__ int   g_cursor[NN];
__device__ int   g_col[NE];
__device__ int   g_bsum[128];
__device__ float g_W12[DH * DOUT];
__device__ float g_b12[DOUT];
__device__ int   g_is64;

// bf16 hi/lo activation planes
__device__ __nv_bfloat16 g_xh[NN * DH],  g_xl[NN * DH];
__device__ __nv_bfloat16 g_ah[NN * DH],  g_al[NN * DH];
__device__ __nv_bfloat16 g_h1h[NN * DH], g_h1l[NN * DH];
__device__ __nv_bfloat16 g_h2h[NN * DH], g_h2l[NN * DH];
// transposed, stacked, split weights: B[n][k], k = [Wl rows | Wr rows]
__device__ __nv_bfloat16 g_B0h[128 * 256], g_B0l[128 * 256];
__device__ __nv_bfloat16 g_B1h[128 * 256], g_B1l[128 * 256];
__device__ __nv_bfloat16 g_B2h[128 * 256], g_B2l[128 * 256];
__device__ __nv_bfloat16 g_B3h[64 * 128],  g_B3l[64 * 128];

__device__ __forceinline__ void bsplit(float v, __nv_bfloat16& h, __nv_bfloat16& l) {
    h = __float2bfloat16(v);
    l = __float2bfloat16(v - __bfloat162float(h));
}

// ---------------- dtype detection (int64 vs int32 edge_index) ----------------
__global__ void k_detect(const int* __restrict__ ei32) {
    if (threadIdx.x == 0 && blockIdx.x == 0) {
        int odd_nonzero = 0;
        for (int i = 0; i < 64; i++)
            if (ei32[2 * i + 1] != 0) odd_nonzero++;
        g_is64 = (odd_nonzero == 0) ? 1 : 0;
    }
}

// ---------------- CSR build ----------------
__global__ void k_zero_cnt() {
    int i = blockIdx.x * blockDim.x + threadIdx.x;
    if (i < NN) g_cnt[i] = 0;
}

__global__ void k_hist(const int* __restrict__ ei32) {
    int e = blockIdx.x * blockDim.x + threadIdx.x;
    if (e >= NE) return;
    int d = g_is64 ? ei32[2 * (NE + e)] : ei32[NE + e];
    if (d >= 0 && d < NN) atomicAdd(&g_cnt[d], 1);
}

__global__ void k_scan1() {
    __shared__ int s[512];
    int i = blockIdx.x * 512 + threadIdx.x;
    int v = (i < NN) ? g_cnt[i] : 0;
    s[threadIdx.x] = v;
    __syncthreads();
    for (int off = 1; off < 512; off <<= 1) {
        int add = (threadIdx.x >= off) ? s[threadIdx.x - off] : 0;
        __syncthreads();
        s[threadIdx.x] += add;
        __syncthreads();
    }
    if (i < NN) g_rowptr[i + 1] = s[threadIdx.x];
    if (threadIdx.x == 511) g_bsum[blockIdx.x] = s[511];
}

__global__ void k_scan2() {
    __shared__ int s[128];
    int t = threadIdx.x;
    int v = (t < 98) ? g_bsum[t] : 0;
    s[t] = v;
    __syncthreads();
    for (int off = 1; off < 128; off <<= 1) {
        int add = (t >= off) ? s[t - off] : 0;
        __syncthreads();
        s[t] += add;
        __syncthreads();
    }
    if (t < 98) g_bsum[t] = s[t] - v;  // exclusive
}

__global__ void k_scan3() {
    int i = blockIdx.x * 512 + threadIdx.x;
    if (i < NN) g_rowptr[i + 1] += g_bsum[blockIdx.x];
    if (i == 0) g_rowptr[0] = 0;
}

__global__ void k_cursor() {
    int i = blockIdx.x * blockDim.x + threadIdx.x;
    if (i < NN) g_cursor[i] = g_rowptr[i];
}

__global__ void k_scatter(const int* __restrict__ ei32) {
    int e = blockIdx.x * blockDim.x + threadIdx.x;
    if (e >= NE) return;
    int is64 = g_is64;
    int d = is64 ? ei32[2 * (NE + e)] : ei32[NE + e];
    int s = is64 ? ei32[2 * e] : ei32[e];
    if (d >= 0 && d < NN && s >= 0 && s < NN) {
        int p = atomicAdd(&g_cursor[d], 1);
        g_col[p] = s;
    }
}

// ---------------- fold post-MLP: W12 = W1@W2, b12 = b1@W2 + b2 ----------------
__global__ void k_w12(const float* __restrict__ W1, const float* __restrict__ W2,
                      const float* __restrict__ b1, const float* __restrict__ b2) {
    int idx = blockIdx.x * blockDim.x + threadIdx.x;
    if (idx < DH * DOUT) {
        int i = idx / DOUT, j = idx % DOUT;
        float s = 0.f;
        for (int k = 0; k < DH; k++) s += W1[i * DH + k] * W2[k * DOUT + j];
        g_W12[idx] = s;
    }
    if (idx < DOUT) {
        float s = b2[idx];
        for (int k = 0; k < DH; k++) s += b1[k] * W2[k * DOUT + idx];
        g_b12[idx] = s;
    }
}

// ---------------- x -> hi/lo bf16 planes ----------------
__global__ void k_cvt_x(const float* __restrict__ x) {
    int idx = blockIdx.x * blockDim.x + threadIdx.x;  // element group of 4
    if (idx >= NN * DH / 4) return;
    float4 v = *(const float4*)(x + idx * 4);
    __nv_bfloat16 h0, h1, h2, h3, l0, l1, l2, l3;
    bsplit(v.x, h0, l0); bsplit(v.y, h1, l1);
    bsplit(v.z, h2, l2); bsplit(v.w, h3, l3);
    __nv_bfloat162 ph01, ph23, pl01, pl23;
    ph01.x = h0; ph01.y = h1; ph23.x = h2; ph23.y = h3;
    pl01.x = l0; pl01.y = l1; pl23.x = l2; pl23.y = l3;
    uint2 uh, ul;
    uh.x = *(uint32_t*)&ph01; uh.y = *(uint32_t*)&ph23;
    ul.x = *(uint32_t*)&pl01; ul.y = *(uint32_t*)&pl23;
    *(uint2*)(g_xh + idx * 4) = uh;
    *(uint2*)(g_xl + idx * 4) = ul;
}

// ---------------- weight transpose+stack+split: B[n][k] ----------------
__global__ void k_wcvt(const float* __restrict__ Wa, const float* __restrict__ Wb,
                       __nv_bfloat16* __restrict__ oh, __nv_bfloat16* __restrict__ ol,
                       int N, int ktot) {
    int idx = blockIdx.x * blockDim.x + threadIdx.x;
    if (idx >= N * ktot) return;
    int n = idx / ktot, k = idx % ktot;
    float w = (k < 128) ? Wa[k * N + n] : Wb[(k - 128) * N + n];
    __nv_bfloat16 h, l;
    bsplit(w, h, l);
    oh[idx] = h; ol[idx] = l;
}

// ---------------- mean aggregation: one warp per node, bf16 hi/lo planes ----
__global__ void k_agg2(const __nv_bfloat16* __restrict__ Ih, const __nv_bfloat16* __restrict__ Il,
                       __nv_bfloat16* __restrict__ Oh, __nv_bfloat16* __restrict__ Ol) {
    int w = (blockIdx.x * blockDim.x + threadIdx.x) >> 5;
    int lane = threadIdx.x & 31;
    if (w >= NN) return;
    int beg = g_rowptr[w], end = g_rowptr[w + 1];
    float a0 = 0.f, a1 = 0.f, a2 = 0.f, a3 = 0.f;
    for (int e = beg; e < end; e++) {
        int s = g_col[e];
        uint2 ph = __ldg((const uint2*)(Ih + (size_t)s * DH + lane * 4));
        uint2 pl = __ldg((const uint2*)(Il + (size_t)s * DH + lane * 4));
        __nv_bfloat162 h01 = *(__nv_bfloat162*)&ph.x;
        __nv_bfloat162 h23 = *(__nv_bfloat162*)&ph.y;
        __nv_bfloat162 l01 = *(__nv_bfloat162*)&pl.x;
        __nv_bfloat162 l23 = *(__nv_bfloat162*)&pl.y;
        a0 += __bfloat162float(h01.x) + __bfloat162float(l01.x);
        a1 += __bfloat162float(h01.y) + __bfloat162float(l01.y);
        a2 += __bfloat162float(h23.x) + __bfloat162float(l23.x);
        a3 += __bfloat162float(h23.y) + __bfloat162float(l23.y);
    }
    float inv = 1.0f / fmaxf((float)(end - beg), 1.0f);
    a0 *= inv; a1 *= inv; a2 *= inv; a3 *= inv;
    __nv_bfloat16 h0, h1, h2, h3, l0, l1, l2, l3;
    bsplit(a0, h0, l0); bsplit(a1, h1, l1);
    bsplit(a2, h2, l2); bsplit(a3, h3, l3);
    __nv_bfloat162 ph01, ph23, pl01, pl23;
    ph01.x = h0; ph01.y = h1; ph23.x = h2; ph23.y = h3;
    pl01.x = l0; pl01.y = l1; pl23.x = l2; pl23.y = l3;
    uint2 uh, ul;
    uh.x = *(uint32_t*)&ph01; uh.y = *(uint32_t*)&ph23;
    ul.x = *(uint32_t*)&pl01; ul.y = *(uint32_t*)&pl23;
    *(uint2*)(Oh + (size_t)w * DH + lane * 4) = uh;
    *(uint2*)(Ol + (size_t)w * DH + lane * 4) = ul;
}

// ---------------- tensor-core GEMM (bf16 hi/lo split, 3 MMA terms) --------
__device__ __forceinline__ void ldx4(uint32_t r[4], const __nv_bfloat16* p) {
    uint32_t a = (uint32_t)__cvta_generic_to_shared(p);
    asm volatile("ldmatrix.sync.aligned.m8n8.x4.shared.b16 {%0,%1,%2,%3}, [%4];"
                 : "=r"(r[0]), "=r"(r[1]), "=r"(r[2]), "=r"(r[3]) : "r"(a));
}

__device__ __forceinline__ void mma_bf16(float c[4], const uint32_t a[4], const uint32_t b[2]) {
    asm volatile(
        "mma.sync.aligned.m16n8k16.row.col.f32.bf16.bf16.f32 "
        "{%0,%1,%2,%3},{%4,%5,%6,%7},{%8,%9},{%0,%1,%2,%3};"
        : "+f"(c[0]), "+f"(c[1]), "+f"(c[2]), "+f"(c[3])
        : "r"(a[0]), "r"(a[1]), "r"(a[2]), "r"(a[3]), "r"(b[0]), "r"(b[1]));
}

// C = act([A1|A2] @ B^T + bias); A planes [M][128]; B planes [BN][KT] (n-major).
// Block: 128 rows x BN cols, 256 threads, 8 warps (4 M x 2 N).
template <int BN, bool DUAL, bool RELU, bool F32OUT>
__launch_bounds__(256)
__global__ void k_mma(const __nv_bfloat16* __restrict__ A1h, const __nv_bfloat16* __restrict__ A1l,
                      const __nv_bfloat16* __restrict__ A2h, const __nv_bfloat16* __restrict__ A2l,
                      const __nv_bfloat16* __restrict__ Bh,  const __nv_bfloat16* __restrict__ Bl,
                      const float* __restrict__ bias,
                      float* __restrict__ Cf,
                      __nv_bfloat16* __restrict__ Ch, __nv_bfloat16* __restrict__ Cl) {
    constexpr int KT = DUAL ? 256 : 128;
    constexpr int AS = 40;       // smem row stride in halves (80B, conflict-free)
    constexpr int WN = BN / 2;   // warp col extent
    constexpr int NF = WN / 8;   // 8-col fragments per warp
    constexpr int NG = WN / 16;  // ldmatrix.x4 groups per warp

    __shared__ __nv_bfloat16 sAh[128 * AS], sAl[128 * AS];
    __shared__ __nv_bfloat16 sBh[BN * AS],  sBl[BN * AS];

    int t = threadIdx.x, lane = t & 31, warp = t >> 5;
    int wm = warp >> 1, wn = warp & 1;
    int m0 = wm * 32, n0w = wn * WN;
    int gr0 = blockIdx.x * 128;

    float acc[2][NF][4];
#pragma unroll
    for (int fm = 0; fm < 2; fm++)
#pragma unroll
        for (int fn = 0; fn < NF; fn++)
#pragma unroll
            for (int j = 0; j < 4; j++) acc[fm][fn][j] = 0.f;

    int arow = lane & 15;
    int ako  = (lane >> 4) << 3;
    int brow = (lane & 7) + ((lane >> 4) << 3);
    int bko  = (lane & 8) ? 8 : 0;

    for (int k0 = 0; k0 < KT; k0 += 32) {
        const __nv_bfloat16* Ah = (DUAL && k0 >= 128) ? A2h : A1h;
        const __nv_bfloat16* Al = (DUAL && k0 >= 128) ? A2l : A1l;
        int kb = k0 & 127;
        // stage A: 512 chunks of 16B per plane
#pragma unroll
        for (int i = 0; i < 2; i++) {
            int ch = t + i * 256;
            int row = ch >> 2, c4 = ch & 3;
            int gr = gr0 + row;
            uint4 vh = {0, 0, 0, 0}, vl = {0, 0, 0, 0};
            if (gr < NN) {
                vh = *(const uint4*)(Ah + (size_t)gr * 128 + kb + c4 * 8);
                vl = *(const uint4*)(Al + (size_t)gr * 128 + kb + c4 * 8);
            }
            *(uint4*)(sAh + row * AS + c4 * 8) = vh;
            *(uint4*)(sAl + row * AS + c4 * 8) = vl;
        }
        // stage B: BN*4 chunks
#pragma unroll
        for (int i = 0; i < (BN * 4) / 256; i++) {
            int ch = t + i * 256;
            int row = ch >> 2, c4 = ch & 3;
            *(uint4*)(sBh + row * AS + c4 * 8) = *(const uint4*)(Bh + (size_t)row * KT + k0 + c4 * 8);
            *(uint4*)(sBl + row * AS + c4 * 8) = *(const uint4*)(Bl + (size_t)row * KT + k0 + c4 * 8);
        }
        __syncthreads();

#pragma unroll
        for (int kk = 0; kk < 32; kk += 16) {
            uint32_t ah[2][4], al[2][4], bh[NF][2], bl[NF][2];
#pragma unroll
            for (int fm = 0; fm < 2; fm++) {
                ldx4(ah[fm], sAh + (m0 + fm * 16 + arow) * AS + kk + ako);
                ldx4(al[fm], sAl + (m0 + fm * 16 + arow) * AS + kk + ako);
            }
#pragma unroll
            for (int g = 0; g < NG; g++) {
                uint32_t r[4];
                ldx4(r, sBh + (n0w + g * 16 + brow) * AS + kk + bko);
                bh[2 * g][0] = r[0]; bh[2 * g][1] = r[1];
                bh[2 * g + 1][0] = r[2]; bh[2 * g + 1][1] = r[3];
                ldx4(r, sBl + (n0w + g * 16 + brow) * AS + kk + bko);
                bl[2 * g][0] = r[0]; bl[2 * g][1] = r[1];
                bl[2 * g + 1][0] = r[2]; bl[2 * g + 1][1] = r[3];
            }
#pragma unroll
            for (int fm = 0; fm < 2; fm++)
#pragma unroll
                for (int fn = 0; fn < NF; fn++) {
                    mma_bf16(acc[fm][fn], ah[fm], bh[fn]);
                    mma_bf16(acc[fm][fn], ah[fm], bl[fn]);
                    mma_bf16(acc[fm][fn], al[fm], bh[fn]);
                }
        }
        __syncthreads();
    }

    // epilogue
    int r4 = lane >> 2, cpair = (lane & 3) * 2;
#pragma unroll
    for (int fm = 0; fm < 2; fm++)
#pragma unroll
        for (int fn = 0; fn < NF; fn++) {
            int col = n0w + fn * 8 + cpair;
            float bb0 = __ldg(bias + col), bb1 = __ldg(bias + col + 1);
            int r0 = gr0 + m0 + fm * 16 + r4;
            int r1 = r0 + 8;
            float v00 = acc[fm][fn][0] + bb0, v01 = acc[fm][fn][1] + bb1;
            float v10 = acc[fm][fn][2] + bb0, v11 = acc[fm][fn][3] + bb1;
            if (RELU) {
                v00 = fmaxf(v00, 0.f); v01 = fmaxf(v01, 0.f);
                v10 = fmaxf(v10, 0.f); v11 = fmaxf(v11, 0.f);
            }
            if (F32OUT) {
                if (r0 < NN) { float2 o = {v00, v01}; *(float2*)(Cf + (size_t)r0 * BN + col) = o; }
                if (r1 < NN) { float2 o = {v10, v11}; *(float2*)(Cf + (size_t)r1 * BN + col) = o; }
            } else {
                __nv_bfloat16 h0, h1, l0, l1;
                if (r0 < NN) {
                    bsplit(v00, h0, l0); bsplit(v01, h1, l1);
                    __nv_bfloat162 ph, pl;
                    ph.x = h0; ph.y = h1; pl.x = l0; pl.y = l1;
                    *(__nv_bfloat162*)(Ch + (size_t)r0 * 128 + col) = ph;
                    *(__nv_bfloat162*)(Cl + (size_t)r0 * 128 + col) = pl;
                }
                if (r1 < NN) {
                    bsplit(v10, h0, l0); bsplit(v11, h1, l1);
                    __nv_bfloat162 ph, pl;
                    ph.x = h0; ph.y = h1; pl.x = l0; pl.y = l1;
                    *(__nv_bfloat162*)(Ch + (size_t)r1 * 128 + col) = ph;
                    *(__nv_bfloat162*)(Cl + (size_t)r1 * 128 + col) = pl;
                }
            }
        }
}

// ---------------- launch ----------------
extern "C" void kernel_launch(void* const* d_in, const int* in_sizes, int n_in,
                              void* d_out, int out_size) {
    const float* x    = (const float*)d_in[0];
    const int*   ei32 = (const int*)d_in[1];
    const float* Wl0 = (const float*)d_in[2];
    const float* bl0 = (const float*)d_in[3];
    const float* Wr0 = (const float*)d_in[4];
    const float* Wl1 = (const float*)d_in[5];
    const float* bl1 = (const float*)d_in[6];
    const float* Wr1 = (const float*)d_in[7];
    const float* Wl2 = (const float*)d_in[8];
    const float* bl2 = (const float*)d_in[9];
    const float* Wr2 = (const float*)d_in[10];
    const float* W1  = (const float*)d_in[11];
    const float* b1  = (const float*)d_in[12];
    const float* W2  = (const float*)d_in[13];
    const float* b2  = (const float*)d_in[14];
    float* out = (float*)d_out;

    __nv_bfloat16 *xh, *xl, *ah, *al, *h1h, *h1l, *h2h, *h2l;
    __nv_bfloat16 *B0h, *B0l, *B1h, *B1l, *B2h, *B2l, *B3h, *B3l;
    float *W12, *b12;
    cudaGetSymbolAddress((void**)&xh, g_xh);   cudaGetSymbolAddress((void**)&xl, g_xl);
    cudaGetSymbolAddress((void**)&ah, g_ah);   cudaGetSymbolAddress((void**)&al, g_al);
    cudaGetSymbolAddress((void**)&h1h, g_h1h); cudaGetSymbolAddress((void**)&h1l, g_h1l);
    cudaGetSymbolAddress((void**)&h2h, g_h2h); cudaGetSymbolAddress((void**)&h2l, g_h2l);
    cudaGetSymbolAddress((void**)&B0h, g_B0h); cudaGetSymbolAddress((void**)&B0l, g_B0l);
    cudaGetSymbolAddress((void**)&B1h, g_B1h); cudaGetSymbolAddress((void**)&B1l, g_B1l);
    cudaGetSymbolAddress((void**)&B2h, g_B2h); cudaGetSymbolAddress((void**)&B2l, g_B2l);
    cudaGetSymbolAddress((void**)&B3h, g_B3h); cudaGetSymbolAddress((void**)&B3l, g_B3l);
    cudaGetSymbolAddress((void**)&W12, g_W12); cudaGetSymbolAddress((void**)&b12, g_b12);

    // dtype probe + CSR build
    k_detect<<<1, 32>>>(ei32);
    k_zero_cnt<<<(NN + 255) / 256, 256>>>();
    k_hist<<<(NE + 255) / 256, 256>>>(ei32);
    k_scan1<<<98, 512>>>();
    k_scan2<<<1, 128>>>();
    k_scan3<<<98, 512>>>();
    k_cursor<<<(NN + 255) / 256, 256>>>();
    k_scatter<<<(NE + 255) / 256, 256>>>(ei32);

    // weight prep
    k_w12<<<(DH * DOUT + 255) / 256, 256>>>(W1, W2, b1, b2);
    k_cvt_x<<<(NN * DH / 4 + 255) / 256, 256>>>(x);
    k_wcvt<<<(128 * 256 + 255) / 256, 256>>>(Wl0, Wr0, B0h, B0l, 128, 256);
    k_wcvt<<<(128 * 256 + 255) / 256, 256>>>(Wl1, Wr1, B1h, B1l, 128, 256);
    k_wcvt<<<(128 * 256 + 255) / 256, 256>>>(Wl2, Wr2, B2h, B2l, 128, 256);
    k_wcvt<<<(64 * 128 + 255) / 256, 256>>>(W12, nullptr, B3h, B3l, 64, 128);

    const int aggBlocks = (NN * 32 + 255) / 256;
    const int mmaBlocks = (NN + 127) / 128;

    // layer 0
    k_agg2<<<aggBlocks, 256>>>(xh, xl, ah, al);
    k_mma<128, true, true, false><<<mmaBlocks, 256>>>(ah, al, xh, xl, B0h, B0l, bl0,
                                                      nullptr, h1h, h1l);
    // layer 1
    k_agg2<<<aggBlocks, 256>>>(h1h, h1l, ah, al);
    k_mma<128, true, true, false><<<mmaBlocks, 256>>>(ah, al, h1h, h1l, B1h, B1l, bl1,
                                                      nullptr, h2h, h2l);
    // layer 2
    k_agg2<<<aggBlocks, 256>>>(h2h, h2l, ah, al);
    k_mma<128, true, true, false><<<mmaBlocks, 256>>>(ah, al, h2h, h2l, B2h, B2l, bl2,
                                                      nullptr, h1h, h1l);
    // post MLP (folded, fp32 out)
    k_mma<64, false, false, true><<<mmaBlocks, 256>>>(h1h, h1l, nullptr, nullptr, B3h, B3l, b12,
                                                      out, nullptr, nullptr);
}

// round 7
// speedup vs baseline: 1.6848x; 1.2938x over previous
#include <cuda_runtime.h>
#include <cuda_fp16.h>
#include <cstdint>

#define NN 50000
#define NE 800000
#define DH 128
#define DOUT 64

// ---------------- device scratch (no allocations allowed) ----------------
__device__ int   g_cnt[NN];
__device__ int   g_rowptr[NN + 1];
__device__ int   g_cursor[NN];
__device__ int   g_col[NE];
__device__ int   g_bsum[128];
__device__ float g_W12[DH * DOUT];
__device__ float g_b12[DOUT];
__device__ int   g_is64;

// fp16 activation planes (single precision plane each)
__device__ __half g_x16[NN * DH];
__device__ __half g_a16[NN * DH];
__device__ __half g_h1_16[NN * DH];
__device__ __half g_h2_16[NN * DH];
// transposed, stacked, hi/lo-split weights: B[n][k], k = [Wl rows | Wr rows]
__device__ __half g_B0h[128 * 256], g_B0l[128 * 256];
__device__ __half g_B1h[128 * 256], g_B1l[128 * 256];
__device__ __half g_B2h[128 * 256], g_B2l[128 * 256];
__device__ __half g_B3h[64 * 128],  g_B3l[64 * 128];

// ---------------- CSR build ----------------
__global__ void k_zero_cnt(const int* __restrict__ ei32) {
    int i = blockIdx.x * blockDim.x + threadIdx.x;
    if (i < NN) g_cnt[i] = 0;
    if (blockIdx.x == 0 && threadIdx.x == 0) {
        int odd_nonzero = 0;
        for (int j = 0; j < 64; j++)
            if (ei32[2 * j + 1] != 0) odd_nonzero++;
        g_is64 = (odd_nonzero == 0) ? 1 : 0;
    }
}

__global__ void k_hist(const int* __restrict__ ei32) {
    int e = blockIdx.x * blockDim.x + threadIdx.x;
    if (e >= NE) return;
    int d = g_is64 ? ei32[2 * (NE + e)] : ei32[NE + e];
    if (d >= 0 && d < NN) atomicAdd(&g_cnt[d], 1);
}

__global__ void k_scan1() {
    __shared__ int s[512];
    int i = blockIdx.x * 512 + threadIdx.x;
    int v = (i < NN) ? g_cnt[i] : 0;
    s[threadIdx.x] = v;
    __syncthreads();
    for (int off = 1; off < 512; off <<= 1) {
        int add = (threadIdx.x >= off) ? s[threadIdx.x - off] : 0;
        __syncthreads();
        s[threadIdx.x] += add;
        __syncthreads();
    }
    if (i < NN) g_rowptr[i + 1] = s[threadIdx.x];
    if (threadIdx.x == 511) g_bsum[blockIdx.x] = s[511];
}

__global__ void k_scan2() {
    __shared__ int s[128];
    int t = threadIdx.x;
    int v = (t < 98) ? g_bsum[t] : 0;
    s[t] = v;
    __syncthreads();
    for (int off = 1; off < 128; off <<= 1) {
        int add = (t >= off) ? s[t - off] : 0;
        __syncthreads();
        s[t] += add;
        __syncthreads();
    }
    if (t < 98) g_bsum[t] = s[t] - v;  // exclusive
}

// scan finalize + cursor init (cursor[i] = final rowptr[i])
__global__ void k_scan3() {
    int i = blockIdx.x * 512 + threadIdx.x;
    if (i < NN) {
        int val = g_rowptr[i + 1] + g_bsum[blockIdx.x];
        g_rowptr[i + 1] = val;
        if (i + 1 < NN) g_cursor[i + 1] = val;
    }
    if (i == 0) { g_rowptr[0] = 0; g_cursor[0] = 0; }
}

__global__ void k_scatter(const int* __restrict__ ei32) {
    int e = blockIdx.x * blockDim.x + threadIdx.x;
    if (e >= NE) return;
    int is64 = g_is64;
    int d = is64 ? ei32[2 * (NE + e)] : ei32[NE + e];
    int s = is64 ? ei32[2 * e] : ei32[e];
    if (d >= 0 && d < NN && s >= 0 && s < NN) {
        int p = atomicAdd(&g_cursor[d], 1);
        g_col[p] = s;
    }
}

// ---------------- fold post-MLP: W12 = W1@W2, b12 = b1@W2 + b2 ----------------
__global__ void k_w12(const float* __restrict__ W1, const float* __restrict__ W2,
                      const float* __restrict__ b1, const float* __restrict__ b2) {
    int idx = blockIdx.x * blockDim.x + threadIdx.x;
    if (idx < DH * DOUT) {
        int i = idx / DOUT, j = idx % DOUT;
        float s = 0.f;
        for (int k = 0; k < DH; k++) s += W1[i * DH + k] * W2[k * DOUT + j];
        g_W12[idx] = s;
    }
    if (idx < DOUT) {
        float s = b2[idx];
        for (int k = 0; k < DH; k++) s += b1[k] * W2[k * DOUT + idx];
        g_b12[idx] = s;
    }
}

// ---------------- x -> fp16 plane ----------------
__global__ void k_cvt_x(const float* __restrict__ x) {
    int idx = blockIdx.x * blockDim.x + threadIdx.x;  // group of 4
    if (idx >= NN * DH / 4) return;
    float4 v = *(const float4*)(x + idx * 4);
    __half2 p01 = __floats2half2_rn(v.x, v.y);
    __half2 p23 = __floats2half2_rn(v.z, v.w);
    uint2 u;
    u.x = *(uint32_t*)&p01; u.y = *(uint32_t*)&p23;
    *(uint2*)(g_x16 + idx * 4) = u;
}

// ---------------- weight transpose+stack+split: B[n][k] ----------------
__global__ void k_wcvt(const float* __restrict__ Wa, const float* __restrict__ Wb,
                       __half* __restrict__ oh, __half* __restrict__ ol,
                       int N, int ktot) {
    int idx = blockIdx.x * blockDim.x + threadIdx.x;
    if (idx >= N * ktot) return;
    int n = idx / ktot, k = idx % ktot;
    float w = (k < 128) ? Wa[k * N + n] : Wb[(k - 128) * N + n];
    __half h = __float2half_rn(w);
    __half l = __float2half_rn(w - __half2float(h));
    oh[idx] = h; ol[idx] = l;
}

// ---------------- mean aggregation: one warp per node, single fp16 plane ----
__global__ void k_agg16(const __half* __restrict__ I, __half* __restrict__ O) {
    int w = (blockIdx.x * blockDim.x + threadIdx.x) >> 5;
    int lane = threadIdx.x & 31;
    if (w >= NN) return;
    int beg = g_rowptr[w], end = g_rowptr[w + 1];
    float a0 = 0.f, a1 = 0.f, a2 = 0.f, a3 = 0.f;
    for (int e = beg; e < end; e++) {
        int s = g_col[e];
        uint2 p = __ldg((const uint2*)(I + (size_t)s * DH + lane * 4));
        __half2 h01 = *(__half2*)&p.x;
        __half2 h23 = *(__half2*)&p.y;
        float2 f01 = __half22float2(h01);
        float2 f23 = __half22float2(h23);
        a0 += f01.x; a1 += f01.y; a2 += f23.x; a3 += f23.y;
    }
    float inv = 1.0f / fmaxf((float)(end - beg), 1.0f);
    __half2 o01 = __floats2half2_rn(a0 * inv, a1 * inv);
    __half2 o23 = __floats2half2_rn(a2 * inv, a3 * inv);
    uint2 u;
    u.x = *(uint32_t*)&o01; u.y = *(uint32_t*)&o23;
    *(uint2*)(O + (size_t)w * DH + lane * 4) = u;
}

// ---------------- tensor-core GEMM (fp16 A, hi/lo-split fp16 B, 2 terms) ----
__device__ __forceinline__ void ldx4(uint32_t r[4], const __half* p) {
    uint32_t a = (uint32_t)__cvta_generic_to_shared(p);
    asm volatile("ldmatrix.sync.aligned.m8n8.x4.shared.b16 {%0,%1,%2,%3}, [%4];"
                 : "=r"(r[0]), "=r"(r[1]), "=r"(r[2]), "=r"(r[3]) : "r"(a));
}

__device__ __forceinline__ void mma_f16(float c[4], const uint32_t a[4], const uint32_t b[2]) {
    asm volatile(
        "mma.sync.aligned.m16n8k16.row.col.f32.f16.f16.f32 "
        "{%0,%1,%2,%3},{%4,%5,%6,%7},{%8,%9},{%0,%1,%2,%3};"
        : "+f"(c[0]), "+f"(c[1]), "+f"(c[2]), "+f"(c[3])
        : "r"(a[0]), "r"(a[1]), "r"(a[2]), "r"(a[3]), "r"(b[0]), "r"(b[1]));
}

// C = act([A1|A2] @ B^T + bias); A fp16 [M][128]; B planes [BN][KT] (n-major).
// Block: 128 rows x BN cols, 256 threads, 8 warps (4 M x 2 N).
template <int BN, bool DUAL, bool RELU, bool F32OUT>
__launch_bounds__(256)
__global__ void k_mma(const __half* __restrict__ A1, const __half* __restrict__ A2,
                      const __half* __restrict__ Bh, const __half* __restrict__ Bl,
                      const float* __restrict__ bias,
                      float* __restrict__ Cf, __half* __restrict__ C16) {
    constexpr int KT = DUAL ? 256 : 128;
    constexpr int AS = 40;       // smem row stride in halves (80B, conflict-free)
    constexpr int WN = BN / 2;   // warp col extent
    constexpr int NF = WN / 8;   // 8-col fragments per warp
    constexpr int NG = WN / 16;  // ldmatrix.x4 groups per warp

    __shared__ __half sA[128 * AS];
    __shared__ __half sBh[BN * AS], sBl[BN * AS];

    int t = threadIdx.x, lane = t & 31, warp = t >> 5;
    int wm = warp >> 1, wn = warp & 1;
    int m0 = wm * 32, n0w = wn * WN;
    int gr0 = blockIdx.x * 128;

    float acc[2][NF][4];
#pragma unroll
    for (int fm = 0; fm < 2; fm++)
#pragma unroll
        for (int fn = 0; fn < NF; fn++)
#pragma unroll
            for (int j = 0; j < 4; j++) acc[fm][fn][j] = 0.f;

    int arow = lane & 15;
    int ako  = (lane >> 4) << 3;
    int brow = (lane & 7) + ((lane >> 4) << 3);
    int bko  = (lane & 8) ? 8 : 0;

    for (int k0 = 0; k0 < KT; k0 += 32) {
        const __half* A = (DUAL && k0 >= 128) ? A2 : A1;
        int kb = k0 & 127;
        // stage A: 512 chunks of 16B
#pragma unroll
        for (int i = 0; i < 2; i++) {
            int ch = t + i * 256;
            int row = ch >> 2, c4 = ch & 3;
            int gr = gr0 + row;
            uint4 v = {0, 0, 0, 0};
            if (gr < NN) v = *(const uint4*)(A + (size_t)gr * 128 + kb + c4 * 8);
            *(uint4*)(sA + row * AS + c4 * 8) = v;
        }
        // stage B: BN*4 chunks per plane
#pragma unroll
        for (int i = 0; i < (BN * 4) / 256; i++) {
            int ch = t + i * 256;
            int row = ch >> 2, c4 = ch & 3;
            *(uint4*)(sBh + row * AS + c4 * 8) = *(const uint4*)(Bh + (size_t)row * KT + k0 + c4 * 8);
            *(uint4*)(sBl + row * AS + c4 * 8) = *(const uint4*)(Bl + (size_t)row * KT + k0 + c4 * 8);
        }
        __syncthreads();

#pragma unroll
        for (int kk = 0; kk < 32; kk += 16) {
            uint32_t a[2][4], bh[NF][2], bl[NF][2];
#pragma unroll
            for (int fm = 0; fm < 2; fm++)
                ldx4(a[fm], sA + (m0 + fm * 16 + arow) * AS + kk + ako);
#pragma unroll
            for (int g = 0; g < NG; g++) {
                uint32_t r[4];
                ldx4(r, sBh + (n0w + g * 16 + brow) * AS + kk + bko);
                bh[2 * g][0] = r[0]; bh[2 * g][1] = r[1];
                bh[2 * g + 1][0] = r[2]; bh[2 * g + 1][1] = r[3];
                ldx4(r, sBl + (n0w + g * 16 + brow) * AS + kk + bko);
                bl[2 * g][0] = r[0]; bl[2 * g][1] = r[1];
                bl[2 * g + 1][0] = r[2]; bl[2 * g + 1][1] = r[3];
            }
#pragma unroll
            for (int fm = 0; fm < 2; fm++)
#pragma unroll
                for (int fn = 0; fn < NF; fn++) {
                    mma_f16(acc[fm][fn], a[fm], bh[fn]);
                    mma_f16(acc[fm][fn], a[fm], bl[fn]);
                }
        }
        __syncthreads();
    }

    // epilogue
    int r4 = lane >> 2, cpair = (lane & 3) * 2;
#pragma unroll
    for (int fm = 0; fm < 2; fm++)
#pragma unroll
        for (int fn = 0; fn < NF; fn++) {
            int col = n0w + fn * 8 + cpair;
            float bb0 = __ldg(bias + col), bb1 = __ldg(bias + col + 1);
            int r0 = gr0 + m0 + fm * 16 + r4;
            int r1 = r0 + 8;
            float v00 = acc[fm][fn][0] + bb0, v01 = acc[fm][fn][1] + bb1;
            float v10 = acc[fm][fn][2] + bb0, v11 = acc[fm][fn][3] + bb1;
            if (RELU) {
                v00 = fmaxf(v00, 0.f); v01 = fmaxf(v01, 0.f);
                v10 = fmaxf(v10, 0.f); v11 = fmaxf(v11, 0.f);
            }
            if (F32OUT) {
                if (r0 < NN) { float2 o = {v00, v01}; *(float2*)(Cf + (size_t)r0 * BN + col) = o; }
                if (r1 < NN) { float2 o = {v10, v11}; *(float2*)(Cf + (size_t)r1 * BN + col) = o; }
            } else {
                if (r0 < NN) *(__half2*)(C16 + (size_t)r0 * 128 + col) = __floats2half2_rn(v00, v01);
                if (r1 < NN) *(__half2*)(C16 + (size_t)r1 * 128 + col) = __floats2half2_rn(v10, v11);
            }
        }
}

// ---------------- launch ----------------
extern "C" void kernel_launch(void* const* d_in, const int* in_sizes, int n_in,
                              void* d_out, int out_size) {
    const float* x    = (const float*)d_in[0];
    const int*   ei32 = (const int*)d_in[1];
    const float* Wl0 = (const float*)d_in[2];
    const float* bl0 = (const float*)d_in[3];
    const float* Wr0 = (const float*)d_in[4];
    const float* Wl1 = (const float*)d_in[5];
    const float* bl1 = (const float*)d_in[6];
    const float* Wr1 = (const float*)d_in[7];
    const float* Wl2 = (const float*)d_in[8];
    const float* bl2 = (const float*)d_in[9];
    const float* Wr2 = (const float*)d_in[10];
    const float* W1  = (const float*)d_in[11];
    const float* b1  = (const float*)d_in[12];
    const float* W2  = (const float*)d_in[13];
    const float* b2  = (const float*)d_in[14];
    float* out = (float*)d_out;

    __half *x16, *a16, *h1, *h2;
    __half *B0h, *B0l, *B1h, *B1l, *B2h, *B2l, *B3h, *B3l;
    float *W12, *b12;
    cudaGetSymbolAddress((void**)&x16, g_x16);
    cudaGetSymbolAddress((void**)&a16, g_a16);
    cudaGetSymbolAddress((void**)&h1, g_h1_16);
    cudaGetSymbolAddress((void**)&h2, g_h2_16);
    cudaGetSymbolAddress((void**)&B0h, g_B0h); cudaGetSymbolAddress((void**)&B0l, g_B0l);
    cudaGetSymbolAddress((void**)&B1h, g_B1h); cudaGetSymbolAddress((void**)&B1l, g_B1l);
    cudaGetSymbolAddress((void**)&B2h, g_B2h); cudaGetSymbolAddress((void**)&B2l, g_B2l);
    cudaGetSymbolAddress((void**)&B3h, g_B3h); cudaGetSymbolAddress((void**)&B3l, g_B3l);
    cudaGetSymbolAddress((void**)&W12, g_W12); cudaGetSymbolAddress((void**)&b12, g_b12);

    // CSR build (+dtype probe folded into zero_cnt, cursor into scan3)
    k_zero_cnt<<<(NN + 255) / 256, 256>>>(ei32);
    k_hist<<<(NE + 255) / 256, 256>>>(ei32);
    k_scan1<<<98, 512>>>();
    k_scan2<<<1, 128>>>();
    k_scan3<<<98, 512>>>();
    k_scatter<<<(NE + 255) / 256, 256>>>(ei32);

    // weight/activation prep
    k_w12<<<(DH * DOUT + 255) / 256, 256>>>(W1, W2, b1, b2);
    k_cvt_x<<<(NN * DH / 4 + 255) / 256, 256>>>(x);
    k_wcvt<<<(128 * 256 + 255) / 256, 256>>>(Wl0, Wr0, B0h, B0l, 128, 256);
    k_wcvt<<<(128 * 256 + 255) / 256, 256>>>(Wl1, Wr1, B1h, B1l, 128, 256);
    k_wcvt<<<(128 * 256 + 255) / 256, 256>>>(Wl2, Wr2, B2h, B2l, 128, 256);
    k_wcvt<<<(64 * 128 + 255) / 256, 256>>>(W12, nullptr, B3h, B3l, 64, 128);

    const int aggBlocks = (NN * 32 + 255) / 256;
    const int mmaBlocks = (NN + 127) / 128;

    // layer 0
    k_agg16<<<aggBlocks, 256>>>(x16, a16);
    k_mma<128, true, true, false><<<mmaBlocks, 256>>>(a16, x16, B0h, B0l, bl0, nullptr, h1);
    // layer 1
    k_agg16<<<aggBlocks, 256>>>(h1, a16);
    k_mma<128, true, true, false><<<mmaBlocks, 256>>>(a16, h1, B1h, B1l, bl1, nullptr, h2);
    // layer 2
    k_agg16<<<aggBlocks, 256>>>(h2, a16);
    k_mma<128, true, true, false><<<mmaBlocks, 256>>>(a16, h2, B2h, B2l, bl2, nullptr, h1);
    // post MLP (folded, fp32 out)
    k_mma<64, false, false, true><<<mmaBlocks, 256>>>(h1, nullptr, B3h, B3l, b12, out, nullptr);
}

// round 8
// speedup vs baseline: 2.0375x; 1.2093x over previous
#include <cuda_runtime.h>
#include <cuda_fp16.h>
#include <cstdint>

#define NN 50000
#define NE 800000
#define DH 128
#define DOUT 64

// ---------------- device scratch (no allocations allowed) ----------------
__device__ int   g_cnt[NN];
__device__ int   g_rowptr[NN + 1];
__device__ int   g_cursor[NN];
__device__ int   g_col[NE];
__device__ int   g_bsum[128];
__device__ float g_W12[DH * DOUT];
__device__ float g_b12[DOUT];
__device__ int   g_is64;

// fp16 activation planes
__device__ __half g_x16[NN * DH];
__device__ __half g_a16[NN * DH];
__device__ __half g_h1_16[NN * DH];
__device__ __half g_h2_16[NN * DH];
// transposed, stacked, hi/lo-split weights: B[n][k], k = [Wl rows | Wr rows]
__device__ __half g_B0h[128 * 256], g_B0l[128 * 256];
__device__ __half g_B1h[128 * 256], g_B1l[128 * 256];
__device__ __half g_B2h[128 * 256], g_B2l[128 * 256];
__device__ __half g_B3h[64 * 128],  g_B3l[64 * 128];

// ---------------- CSR build ----------------
__global__ void k_zero_cnt(const int* __restrict__ ei32) {
    int i = blockIdx.x * blockDim.x + threadIdx.x;
    if (i < NN) g_cnt[i] = 0;
    if (blockIdx.x == 0 && threadIdx.x == 0) {
        int odd_nonzero = 0;
        for (int j = 0; j < 64; j++)
            if (ei32[2 * j + 1] != 0) odd_nonzero++;
        g_is64 = (odd_nonzero == 0) ? 1 : 0;
    }
}

__global__ void k_hist(const int* __restrict__ ei32) {
    int e = blockIdx.x * blockDim.x + threadIdx.x;
    if (e >= NE) return;
    int d = g_is64 ? ei32[2 * (NE + e)] : ei32[NE + e];
    if (d >= 0 && d < NN) atomicAdd(&g_cnt[d], 1);
}

__global__ void k_scan1() {
    __shared__ int s[512];
    int i = blockIdx.x * 512 + threadIdx.x;
    int v = (i < NN) ? g_cnt[i] : 0;
    s[threadIdx.x] = v;
    __syncthreads();
    for (int off = 1; off < 512; off <<= 1) {
        int add = (threadIdx.x >= off) ? s[threadIdx.x - off] : 0;
        __syncthreads();
        s[threadIdx.x] += add;
        __syncthreads();
    }
    if (i < NN) g_rowptr[i + 1] = s[threadIdx.x];
    if (threadIdx.x == 511) g_bsum[blockIdx.x] = s[511];
}

__global__ void k_scan2() {
    __shared__ int s[128];
    int t = threadIdx.x;
    int v = (t < 98) ? g_bsum[t] : 0;
    s[t] = v;
    __syncthreads();
    for (int off = 1; off < 128; off <<= 1) {
        int add = (t >= off) ? s[t - off] : 0;
        __syncthreads();
        s[t] += add;
        __syncthreads();
    }
    if (t < 98) g_bsum[t] = s[t] - v;  // exclusive
}

// scan finalize + cursor init
__global__ void k_scan3() {
    int i = blockIdx.x * 512 + threadIdx.x;
    if (i < NN) {
        int val = g_rowptr[i + 1] + g_bsum[blockIdx.x];
        g_rowptr[i + 1] = val;
        if (i + 1 < NN) g_cursor[i + 1] = val;
    }
    if (i == 0) { g_rowptr[0] = 0; g_cursor[0] = 0; }
}

__global__ void k_scatter(const int* __restrict__ ei32) {
    int e = blockIdx.x * blockDim.x + threadIdx.x;
    if (e >= NE) return;
    int is64 = g_is64;
    int d = is64 ? ei32[2 * (NE + e)] : ei32[NE + e];
    int s = is64 ? ei32[2 * e] : ei32[e];
    if (d >= 0 && d < NN && s >= 0 && s < NN) {
        int p = atomicAdd(&g_cursor[d], 1);
        g_col[p] = s;
    }
}

// ---------------- fold post-MLP: W12 = W1@W2, b12 = b1@W2 + b2 ----------------
__global__ void k_w12(const float* __restrict__ W1, const float* __restrict__ W2,
                      const float* __restrict__ b1, const float* __restrict__ b2) {
    int idx = blockIdx.x * blockDim.x + threadIdx.x;
    if (idx < DH * DOUT) {
        int i = idx / DOUT, j = idx % DOUT;
        float s = 0.f;
        for (int k = 0; k < DH; k++) s += W1[i * DH + k] * W2[k * DOUT + j];
        g_W12[idx] = s;
    }
    if (idx < DOUT) {
        float s = b2[idx];
        for (int k = 0; k < DH; k++) s += b1[k] * W2[k * DOUT + idx];
        g_b12[idx] = s;
    }
}

// ---------------- fused prep: x->fp16, 4x weight transpose+stack+split -------
__device__ __forceinline__ void wseg(const float* __restrict__ Wa, const float* __restrict__ Wb,
                                     __half* __restrict__ oh, __half* __restrict__ ol,
                                     int blk, int N, int ktot) {
    int idx = blk * 256 + threadIdx.x;
    if (idx >= N * ktot) return;
    int n = idx / ktot, k = idx % ktot;
    float w = (k < 128) ? Wa[k * N + n] : Wb[(k - 128) * N + n];
    __half h = __float2half_rn(w);
    __half l = __float2half_rn(w - __half2float(h));
    oh[idx] = h; ol[idx] = l;
}

#define CVT_BLOCKS 6250  // NN*DH/4/256
__global__ void k_prep(const float* __restrict__ x,
                       const float* __restrict__ Wl0, const float* __restrict__ Wr0,
                       const float* __restrict__ Wl1, const float* __restrict__ Wr1,
                       const float* __restrict__ Wl2, const float* __restrict__ Wr2) {
    int b = blockIdx.x;
    if (b < CVT_BLOCKS) {
        int idx = b * 256 + threadIdx.x;  // group of 4 floats
        float4 v = *(const float4*)(x + idx * 4);
        __half2 p01 = __floats2half2_rn(v.x, v.y);
        __half2 p23 = __floats2half2_rn(v.z, v.w);
        uint2 u;
        u.x = *(uint32_t*)&p01; u.y = *(uint32_t*)&p23;
        *(uint2*)(g_x16 + idx * 4) = u;
    } else if (b < CVT_BLOCKS + 128) {
        wseg(Wl0, Wr0, g_B0h, g_B0l, b - CVT_BLOCKS, 128, 256);
    } else if (b < CVT_BLOCKS + 256) {
        wseg(Wl1, Wr1, g_B1h, g_B1l, b - (CVT_BLOCKS + 128), 128, 256);
    } else if (b < CVT_BLOCKS + 384) {
        wseg(Wl2, Wr2, g_B2h, g_B2l, b - (CVT_BLOCKS + 256), 128, 256);
    } else {
        wseg(g_W12, nullptr, g_B3h, g_B3l, b - (CVT_BLOCKS + 384), 64, 128);
    }
}
#define PREP_BLOCKS (CVT_BLOCKS + 384 + 32)

// ---------------- mean aggregation: half-warp per node, uint4 loads ----------
__device__ __forceinline__ void hacc(float* a, uint4 p) {
    __half2* hp = (__half2*)&p;
#pragma unroll
    for (int j = 0; j < 4; j++) {
        float2 f = __half22float2(hp[j]);
        a[2 * j] += f.x; a[2 * j + 1] += f.y;
    }
}

__global__ void k_agg16(const __half* __restrict__ I, __half* __restrict__ O) {
    int hw = (blockIdx.x * blockDim.x + threadIdx.x) >> 4;  // node id
    int lane = threadIdx.x & 15;
    if (hw >= NN) return;
    int beg = g_rowptr[hw], end = g_rowptr[hw + 1];
    float a[8] = {0.f, 0.f, 0.f, 0.f, 0.f, 0.f, 0.f, 0.f};
    int e = beg;
    for (; e + 1 < end; e += 2) {
        int s0 = g_col[e], s1 = g_col[e + 1];
        uint4 p0 = __ldg((const uint4*)(I + (size_t)s0 * DH + lane * 8));
        uint4 p1 = __ldg((const uint4*)(I + (size_t)s1 * DH + lane * 8));
        hacc(a, p0); hacc(a, p1);
    }
    if (e < end) {
        int s0 = g_col[e];
        hacc(a, __ldg((const uint4*)(I + (size_t)s0 * DH + lane * 8)));
    }
    float inv = 1.0f / fmaxf((float)(end - beg), 1.0f);
    __half2 o[4];
#pragma unroll
    for (int j = 0; j < 4; j++)
        o[j] = __floats2half2_rn(a[2 * j] * inv, a[2 * j + 1] * inv);
    uint4 u;
    u.x = *(uint32_t*)&o[0]; u.y = *(uint32_t*)&o[1];
    u.z = *(uint32_t*)&o[2]; u.w = *(uint32_t*)&o[3];
    *(uint4*)(O + (size_t)hw * DH + lane * 8) = u;
}

// ---------------- tensor-core GEMM: cp.async 2-stage pipeline ----------------
__device__ __forceinline__ void ldx4(uint32_t r[4], const __half* p) {
    uint32_t a = (uint32_t)__cvta_generic_to_shared(p);
    asm volatile("ldmatrix.sync.aligned.m8n8.x4.shared.b16 {%0,%1,%2,%3}, [%4];"
                 : "=r"(r[0]), "=r"(r[1]), "=r"(r[2]), "=r"(r[3]) : "r"(a));
}

__device__ __forceinline__ void mma_f16(float c[4], const uint32_t a[4], const uint32_t b[2]) {
    asm volatile(
        "mma.sync.aligned.m16n8k16.row.col.f32.f16.f16.f32 "
        "{%0,%1,%2,%3},{%4,%5,%6,%7},{%8,%9},{%0,%1,%2,%3};"
        : "+f"(c[0]), "+f"(c[1]), "+f"(c[2]), "+f"(c[3])
        : "r"(a[0]), "r"(a[1]), "r"(a[2]), "r"(a[3]), "r"(b[0]), "r"(b[1]));
}

__device__ __forceinline__ void cpa16(uint32_t dst, const void* src, bool v) {
    int sz = v ? 16 : 0;
    asm volatile("cp.async.cg.shared.global [%0], [%1], 16, %2;"
                 :: "r"(dst), "l"(src), "r"(sz) : "memory");
}
#define CP_COMMIT() asm volatile("cp.async.commit_group;" ::: "memory")
#define CP_WAIT1()  asm volatile("cp.async.wait_group 1;" ::: "memory")

// C = act([A1|A2] @ B^T + bias); A fp16 [M][128]; B planes [BN][KT] (n-major).
// 128 rows x BN cols per CTA, 256 threads, 8 warps (4 M x 2 N), double-buffered.
template <int BN, bool DUAL, bool RELU, bool F32OUT>
__launch_bounds__(256)
__global__ void k_mma(const __half* __restrict__ A1, const __half* __restrict__ A2,
                      const __half* __restrict__ Bh, const __half* __restrict__ Bl,
                      const float* __restrict__ bias,
                      float* __restrict__ Cf, __half* __restrict__ C16) {
    constexpr int KT  = DUAL ? 256 : 128;
    constexpr int NCH = KT / 32;
    constexpr int AS  = 40;                 // smem row stride in halves (80B)
    constexpr int ABYTES = 128 * AS * 2;    // 10240
    constexpr int BBYTES = BN * AS * 2;
    constexpr int WN = BN / 2;
    constexpr int NF = WN / 8;
    constexpr int NG = WN / 16;

    extern __shared__ __align__(16) char smem[];
    uint32_t sb = (uint32_t)__cvta_generic_to_shared(smem);

    int t = threadIdx.x, lane = t & 31, warp = t >> 5;
    int wm = warp >> 1, wn = warp & 1;
    int m0 = wm * 32, n0w = wn * WN;
    int gr0 = blockIdx.x * 128;

    float acc[2][NF][4];
#pragma unroll
    for (int fm = 0; fm < 2; fm++)
#pragma unroll
        for (int fn = 0; fn < NF; fn++)
#pragma unroll
            for (int j = 0; j < 4; j++) acc[fm][fn][j] = 0.f;

    int arow = lane & 15;
    int ako  = (lane >> 4) << 3;
    int brow = (lane & 7) + ((lane >> 4) << 3);
    int bko  = (lane & 8) ? 8 : 0;

    // ---- stage chunk ch into buffer b ----
    auto stage = [&](int ch, int b) {
        const __half* A = (DUAL && ch >= 4) ? A2 : A1;
        int kb = (ch * 32) & 127;
        int k0 = ch * 32;
        uint32_t sAb  = sb + b * ABYTES;
        uint32_t sBhb = sb + 2 * ABYTES + b * BBYTES;
        uint32_t sBlb = sb + 2 * ABYTES + 2 * BBYTES + b * BBYTES;
#pragma unroll
        for (int i = 0; i < 2; i++) {
            int c = t + i * 256;
            int row = c >> 2, c4 = c & 3;
            int gr = gr0 + row;
            cpa16(sAb + (row * AS + c4 * 8) * 2,
                  A + (size_t)gr * 128 + kb + c4 * 8, gr < NN);
        }
#pragma unroll
        for (int i = 0; i < (BN * 4) / 256; i++) {
            int c = t + i * 256;
            int row = c >> 2, c4 = c & 3;
            cpa16(sBhb + (row * AS + c4 * 8) * 2,
                  Bh + (size_t)row * KT + k0 + c4 * 8, true);
            cpa16(sBlb + (row * AS + c4 * 8) * 2,
                  Bl + (size_t)row * KT + k0 + c4 * 8, true);
        }
    };

    stage(0, 0);
    CP_COMMIT();

    for (int ch = 0; ch < NCH; ch++) {
        if (ch + 1 < NCH) stage(ch + 1, (ch + 1) & 1);
        CP_COMMIT();
        CP_WAIT1();
        __syncthreads();

        const __half* sA  = (const __half*)(smem + (ch & 1) * ABYTES);
        const __half* sBh = (const __half*)(smem + 2 * ABYTES + (ch & 1) * BBYTES);
        const __half* sBl = (const __half*)(smem + 2 * ABYTES + 2 * BBYTES + (ch & 1) * BBYTES);

#pragma unroll
        for (int kk = 0; kk < 32; kk += 16) {
            uint32_t a[2][4], bh[NF][2], bl[NF][2];
#pragma unroll
            for (int fm = 0; fm < 2; fm++)
                ldx4(a[fm], sA + (m0 + fm * 16 + arow) * AS + kk + ako);
#pragma unroll
            for (int g = 0; g < NG; g++) {
                uint32_t r[4];
                ldx4(r, sBh + (n0w + g * 16 + brow) * AS + kk + bko);
                bh[2 * g][0] = r[0]; bh[2 * g][1] = r[1];
                bh[2 * g + 1][0] = r[2]; bh[2 * g + 1][1] = r[3];
                ldx4(r, sBl + (n0w + g * 16 + brow) * AS + kk + bko);
                bl[2 * g][0] = r[0]; bl[2 * g][1] = r[1];
                bl[2 * g + 1][0] = r[2]; bl[2 * g + 1][1] = r[3];
            }
#pragma unroll
            for (int fm = 0; fm < 2; fm++)
#pragma unroll
                for (int fn = 0; fn < NF; fn++) {
                    mma_f16(acc[fm][fn], a[fm], bh[fn]);
                    mma_f16(acc[fm][fn], a[fm], bl[fn]);
                }
        }
        __syncthreads();
    }

    // epilogue
    int r4 = lane >> 2, cpair = (lane & 3) * 2;
#pragma unroll
    for (int fm = 0; fm < 2; fm++)
#pragma unroll
        for (int fn = 0; fn < NF; fn++) {
            int col = n0w + fn * 8 + cpair;
            float bb0 = __ldg(bias + col), bb1 = __ldg(bias + col + 1);
            int r0 = gr0 + m0 + fm * 16 + r4;
            int r1 = r0 + 8;
            float v00 = acc[fm][fn][0] + bb0, v01 = acc[fm][fn][1] + bb1;
            float v10 = acc[fm][fn][2] + bb0, v11 = acc[fm][fn][3] + bb1;
            if (RELU) {
                v00 = fmaxf(v00, 0.f); v01 = fmaxf(v01, 0.f);
                v10 = fmaxf(v10, 0.f); v11 = fmaxf(v11, 0.f);
            }
            if (F32OUT) {
                if (r0 < NN) { float2 o = {v00, v01}; *(float2*)(Cf + (size_t)r0 * BN + col) = o; }
                if (r1 < NN) { float2 o = {v10, v11}; *(float2*)(Cf + (size_t)r1 * BN + col) = o; }
            } else {
                if (r0 < NN) *(__half2*)(C16 + (size_t)r0 * 128 + col) = __floats2half2_rn(v00, v01);
                if (r1 < NN) *(__half2*)(C16 + (size_t)r1 * 128 + col) = __floats2half2_rn(v10, v11);
            }
        }
}

#define MMA_SMEM_128 (2 * 10240 + 4 * 128 * 40 * 2)  // 61440
#define MMA_SMEM_64  (2 * 10240 + 4 * 64 * 40 * 2)   // 40960

// ---------------- launch ----------------
extern "C" void kernel_launch(void* const* d_in, const int* in_sizes, int n_in,
                              void* d_out, int out_size) {
    const float* x    = (const float*)d_in[0];
    const int*   ei32 = (const int*)d_in[1];
    const float* Wl0 = (const float*)d_in[2];
    const float* bl0 = (const float*)d_in[3];
    const float* Wr0 = (const float*)d_in[4];
    const float* Wl1 = (const float*)d_in[5];
    const float* bl1 = (const float*)d_in[6];
    const float* Wr1 = (const float*)d_in[7];
    const float* Wl2 = (const float*)d_in[8];
    const float* bl2 = (const float*)d_in[9];
    const float* Wr2 = (const float*)d_in[10];
    const float* W1  = (const float*)d_in[11];
    const float* b1  = (const float*)d_in[12];
    const float* W2  = (const float*)d_in[13];
    const float* b2  = (const float*)d_in[14];
    float* out = (float*)d_out;

    __half *x16, *a16, *h1, *h2;
    __half *B0h, *B0l, *B1h, *B1l, *B2h, *B2l, *B3h, *B3l;
    float *b12;
    cudaGetSymbolAddress((void**)&x16, g_x16);
    cudaGetSymbolAddress((void**)&a16, g_a16);
    cudaGetSymbolAddress((void**)&h1, g_h1_16);
    cudaGetSymbolAddress((void**)&h2, g_h2_16);
    cudaGetSymbolAddress((void**)&B0h, g_B0h); cudaGetSymbolAddress((void**)&B0l, g_B0l);
    cudaGetSymbolAddress((void**)&B1h, g_B1h); cudaGetSymbolAddress((void**)&B1l, g_B1l);
    cudaGetSymbolAddress((void**)&B2h, g_B2h); cudaGetSymbolAddress((void**)&B2l, g_B2l);
    cudaGetSymbolAddress((void**)&B3h, g_B3h); cudaGetSymbolAddress((void**)&B3l, g_B3l);
    cudaGetSymbolAddress((void**)&b12, g_b12);

    cudaFuncSetAttribute(k_mma<128, true, true, false>,
                         cudaFuncAttributeMaxDynamicSharedMemorySize, MMA_SMEM_128);
    cudaFuncSetAttribute(k_mma<64, false, false, true>,
                         cudaFuncAttributeMaxDynamicSharedMemorySize, MMA_SMEM_64);

    // CSR build
    k_zero_cnt<<<(NN + 255) / 256, 256>>>(ei32);
    k_hist<<<(NE + 255) / 256, 256>>>(ei32);
    k_scan1<<<98, 512>>>();
    k_scan2<<<1, 128>>>();
    k_scan3<<<98, 512>>>();
    k_scatter<<<(NE + 255) / 256, 256>>>(ei32);

    // prep: W12 fold, then fused conversion kernel
    k_w12<<<(DH * DOUT + 255) / 256, 256>>>(W1, W2, b1, b2);
    k_prep<<<PREP_BLOCKS, 256>>>(x, Wl0, Wr0, Wl1, Wr1, Wl2, Wr2);

    const int aggBlocks = (NN * 16 + 255) / 256;
    const int mmaBlocks = (NN + 127) / 128;

    // layer 0
    k_agg16<<<aggBlocks, 256>>>(x16, a16);
    k_mma<128, true, true, false><<<mmaBlocks, 256, MMA_SMEM_128>>>(a16, x16, B0h, B0l, bl0, nullptr, h1);
    // layer 1
    k_agg16<<<aggBlocks, 256>>>(h1, a16);
    k_mma<128, true, true, false><<<mmaBlocks, 256, MMA_SMEM_128>>>(a16, h1, B1h, B1l, bl1, nullptr, h2);
    // layer 2
    k_agg16<<<aggBlocks, 256>>>(h2, a16);
    k_mma<128, true, true, false><<<mmaBlocks, 256, MMA_SMEM_128>>>(a16, h2, B2h, B2l, bl2, nullptr, h1);
    // post MLP (folded, fp32 out)
    k_mma<64, false, false, true><<<mmaBlocks, 256, MMA_SMEM_64>>>(h1, nullptr, B3h, B3l, b12, out, nullptr);
}